// round 1
// baseline (speedup 1.0000x reference)
#include <cuda_runtime.h>
#include <math_constants.h>

// Problem constants
// x: (2, 2048, 1024) fp32 ; w_qkv: (1024, 3072) ; w_out: (1024, 1024)
// out: (2, 2048, 1024) fp32
#define BB 2
#define SS 2048
#define DD 1024
#define HH 16
#define HDIM 64
#define MROWS (BB * SS)      // 4096
#define NQKV (3 * DD)        // 3072

// Scratch (allocation-free rule: __device__ globals)
__device__ float g_qkv[(size_t)MROWS * NQKV];   // (B*S, 3D): q | k | v
__device__ float g_attn[(size_t)MROWS * DD];    // (B, S, H, HD) contiguous == (B*S, D)

// ---------------------------------------------------------------------------
// Tiled SGEMM: C[M,N] = A[M,K] @ B[K,N], 128x128 block, BK=16, 8x8 microtile.
// OUTPROJ=false: A = param (x), C = g_qkv
// OUTPROJ=true : A = g_attn,    C = param (d_out)
// ---------------------------------------------------------------------------
template <bool OUTPROJ>
__global__ __launch_bounds__(256)
void sgemm128(int M_, int N_, int K_,
              const float* __restrict__ Ap,
              const float* __restrict__ Bm,
              float* __restrict__ Cp)
{
    const float* A = OUTPROJ ? (const float*)g_attn : Ap;
    float* C = OUTPROJ ? Cp : (float*)g_qkv;

    __shared__ float As[16][128];   // transposed A tile: As[k][m]
    __shared__ float Bs[16][128];   // Bs[k][n]

    const int tid = threadIdx.x;
    const int bm = blockIdx.y * 128;
    const int bn = blockIdx.x * 128;
    const int tx = tid & 15;        // 0..15 -> 8 cols each
    const int ty = tid >> 4;        // 0..15 -> 8 rows each

    float acc[8][8] = {};

    for (int k0 = 0; k0 < K_; k0 += 16) {
        // Load A tile 128x16 (512 float4, 2 per thread), store transposed
        #pragma unroll
        for (int p = 0; p < 2; p++) {
            int f4 = tid + p * 256;
            int r = f4 >> 2;
            int c = (f4 & 3) << 2;
            float4 v = *reinterpret_cast<const float4*>(
                A + (size_t)(bm + r) * K_ + k0 + c);
            As[c + 0][r] = v.x;
            As[c + 1][r] = v.y;
            As[c + 2][r] = v.z;
            As[c + 3][r] = v.w;
        }
        // Load B tile 16x128 (512 float4, 2 per thread), row-major
        #pragma unroll
        for (int p = 0; p < 2; p++) {
            int f4 = tid + p * 256;
            int r = f4 >> 5;
            int c = (f4 & 31) << 2;
            *reinterpret_cast<float4*>(&Bs[r][c]) =
                *reinterpret_cast<const float4*>(
                    Bm + (size_t)(k0 + r) * N_ + bn + c);
        }
        __syncthreads();

        #pragma unroll
        for (int kk = 0; kk < 16; kk++) {
            float af[8], bf[8];
            float4 a0 = *reinterpret_cast<const float4*>(&As[kk][ty * 8]);
            float4 a1 = *reinterpret_cast<const float4*>(&As[kk][ty * 8 + 4]);
            float4 b0 = *reinterpret_cast<const float4*>(&Bs[kk][tx * 8]);
            float4 b1 = *reinterpret_cast<const float4*>(&Bs[kk][tx * 8 + 4]);
            af[0] = a0.x; af[1] = a0.y; af[2] = a0.z; af[3] = a0.w;
            af[4] = a1.x; af[5] = a1.y; af[6] = a1.z; af[7] = a1.w;
            bf[0] = b0.x; bf[1] = b0.y; bf[2] = b0.z; bf[3] = b0.w;
            bf[4] = b1.x; bf[5] = b1.y; bf[6] = b1.z; bf[7] = b1.w;
            #pragma unroll
            for (int i = 0; i < 8; i++)
                #pragma unroll
                for (int j = 0; j < 8; j++)
                    acc[i][j] = fmaf(af[i], bf[j], acc[i][j]);
        }
        __syncthreads();
    }

    #pragma unroll
    for (int i = 0; i < 8; i++) {
        float* crow = C + (size_t)(bm + ty * 8 + i) * N_ + bn + tx * 8;
        *reinterpret_cast<float4*>(crow) =
            make_float4(acc[i][0], acc[i][1], acc[i][2], acc[i][3]);
        *reinterpret_cast<float4*>(crow + 4) =
            make_float4(acc[i][4], acc[i][5], acc[i][6], acc[i][7]);
    }
}

// ---------------------------------------------------------------------------
// Causal flash attention, one (batch, head, 64-row query tile) per block.
// 256 threads = 8 warps; warp w owns query rows [8w, 8w+8), lane l owns
// columns {l, l+32} of both the 64-wide score tile and the 64-wide HD tile.
// Smem: Qs (64x64), KPs (K^T during scores, then P), Vs (64x64) = 48KB exact.
// ---------------------------------------------------------------------------
__global__ __launch_bounds__(256)
void attn64(void)
{
    __shared__ float Qs[64][64];    // Qs[row][d], broadcast reads -> no pad needed
    __shared__ float KPs[64][64];   // phase 1: K^T[d][c]; phase 2: P[row][kc]
    __shared__ float Vs[64][64];    // Vs[kc][d], read Vs[kc][l] -> bank-clean

    const int tid = threadIdx.x;
    const int w = tid >> 5;
    const int l = tid & 31;
    const int qt = blockIdx.x;      // 0..31 query tile
    const int h  = blockIdx.y;      // 0..15
    const int b  = blockIdx.z;      // 0..1
    const int ldq = NQKV;           // 3072

    const float* qkv = g_qkv;
    const float* qbase = qkv + ((size_t)b * SS + (size_t)qt * 64) * ldq + h * HDIM;
    const float* kb0   = qkv + (size_t)b * SS * ldq + DD + h * HDIM;
    const float* vb0   = qkv + (size_t)b * SS * ldq + 2 * DD + h * HDIM;

    // Load Q tile, pre-scaled by HD^-0.5 = 0.125
    for (int idx = tid; idx < 64 * 16; idx += 256) {
        int r = idx >> 4;
        int c = (idx & 15) << 2;
        float4 v = *reinterpret_cast<const float4*>(qbase + (size_t)r * ldq + c);
        Qs[r][c + 0] = v.x * 0.125f;
        Qs[r][c + 1] = v.y * 0.125f;
        Qs[r][c + 2] = v.z * 0.125f;
        Qs[r][c + 3] = v.w * 0.125f;
    }

    float o0[8] = {}, o1[8] = {};
    float mrow[8], lrow[8];
    #pragma unroll
    for (int i = 0; i < 8; i++) { mrow[i] = -CUDART_INF_F; lrow[i] = 0.f; }

    for (int kt = 0; kt <= qt; kt++) {
        __syncthreads();  // protect KPs(P)/Vs from previous iteration's readers

        const float* kb = kb0 + (size_t)kt * 64 * ldq;
        const float* vb = vb0 + (size_t)kt * 64 * ldq;

        // K stored transposed: KPs[d][c]. Mapping keeps STS bank-clean
        // (lane -> key row), gmem side is L2-resident so coalescing loss is ok.
        for (int idx = tid; idx < 64 * 16; idx += 256) {
            int r = idx & 63;            // key row
            int c = (idx >> 6) << 2;     // d chunk
            float4 kv = *reinterpret_cast<const float4*>(kb + (size_t)r * ldq + c);
            KPs[c + 0][r] = kv.x;
            KPs[c + 1][r] = kv.y;
            KPs[c + 2][r] = kv.z;
            KPs[c + 3][r] = kv.w;
        }
        // V normal layout, coalesced
        for (int idx = tid; idx < 64 * 16; idx += 256) {
            int r = idx >> 4;
            int c = (idx & 15) << 2;
            *reinterpret_cast<float4*>(&Vs[r][c]) =
                *reinterpret_cast<const float4*>(vb + (size_t)r * ldq + c);
        }
        __syncthreads();

        // S = Q @ K^T  (per thread: 8 rows x 2 cols)
        float s0[8] = {}, s1[8] = {};
        #pragma unroll 8
        for (int d = 0; d < 64; d++) {
            float k0v = KPs[d][l];
            float k1v = KPs[d][l + 32];
            #pragma unroll
            for (int i = 0; i < 8; i++) {
                float q = Qs[w * 8 + i][d];
                s0[i] = fmaf(q, k0v, s0[i]);
                s1[i] = fmaf(q, k1v, s1[i]);
            }
        }

        // Causal mask only on the diagonal tile
        if (kt == qt) {
            #pragma unroll
            for (int i = 0; i < 8; i++) {
                int rl = w * 8 + i;
                if (l > rl)      s0[i] = -CUDART_INF_F;
                if (l + 32 > rl) s1[i] = -CUDART_INF_F;
            }
        }

        __syncthreads();  // all warps done reading K^T -> reuse KPs as P

        // Online softmax (row stats replicated via warp shuffles)
        #pragma unroll
        for (int i = 0; i < 8; i++) {
            float mx = fmaxf(s0[i], s1[i]);
            #pragma unroll
            for (int off = 16; off; off >>= 1)
                mx = fmaxf(mx, __shfl_xor_sync(0xffffffffu, mx, off));
            float mnew = fmaxf(mrow[i], mx);
            float corr = __expf(mrow[i] - mnew);   // exp(-inf)=0 on first tile
            float p0 = __expf(s0[i] - mnew);
            float p1 = __expf(s1[i] - mnew);
            float rs = p0 + p1;
            #pragma unroll
            for (int off = 16; off; off >>= 1)
                rs += __shfl_xor_sync(0xffffffffu, rs, off);
            lrow[i] = lrow[i] * corr + rs;
            mrow[i] = mnew;
            o0[i] *= corr;
            o1[i] *= corr;
            KPs[w * 8 + i][l]      = p0;   // P rows owned + read by this warp only
            KPs[w * 8 + i][l + 32] = p1;
        }
        __syncwarp();

        // O += P @ V
        #pragma unroll 8
        for (int kc = 0; kc < 64; kc++) {
            float v0 = Vs[kc][l];
            float v1 = Vs[kc][l + 32];
            #pragma unroll
            for (int i = 0; i < 8; i++) {
                float p = KPs[w * 8 + i][kc];   // broadcast load
                o0[i] = fmaf(p, v0, o0[i]);
                o1[i] = fmaf(p, v1, o1[i]);
            }
        }
    }

    // Epilogue: normalize and write (B,S,H,HD) == (B*S, D)
    float* ob = g_attn + ((size_t)b * SS + (size_t)qt * 64) * DD + h * HDIM;
    #pragma unroll
    for (int i = 0; i < 8; i++) {
        float inv = 1.0f / lrow[i];
        ob[(size_t)(w * 8 + i) * DD + l]      = o0[i] * inv;
        ob[(size_t)(w * 8 + i) * DD + l + 32] = o1[i] * inv;
    }
}

// ---------------------------------------------------------------------------
extern "C" void kernel_launch(void* const* d_in, const int* in_sizes, int n_in,
                              void* d_out, int out_size)
{
    const float* x    = (const float*)d_in[0];  // (2,2048,1024)
    const float* wqkv = (const float*)d_in[1];  // (1024,3072)
    const float* wout = (const float*)d_in[2];  // (1024,1024)
    float* out = (float*)d_out;                 // (2,2048,1024)

    // 1) QKV projection: (4096,1024) @ (1024,3072) -> g_qkv
    sgemm128<false><<<dim3(NQKV / 128, MROWS / 128), 256>>>(
        MROWS, NQKV, DD, x, wqkv, nullptr);

    // 2) Causal attention per (b, h, qtile) -> g_attn
    attn64<<<dim3(SS / 64, HH, BB), 256>>>();

    // 3) Output projection: (4096,1024) @ (1024,1024) -> d_out
    sgemm128<true><<<dim3(DD / 128, MROWS / 128), 256>>>(
        MROWS, DD, DD, nullptr, wout, out);
}

// round 2
// speedup vs baseline: 1.5731x; 1.5731x over previous
#include <cuda_runtime.h>
#include <math_constants.h>
#include <stdint.h>

// Problem constants
#define BB 2
#define SS 2048
#define DD 1024
#define HH 16
#define HDIM 64
#define MROWS (BB * SS)      // 4096
#define NQKV (3 * DD)        // 3072

// Scratch (allocation-free rule: __device__ globals)
__device__ float g_qkv[(size_t)MROWS * NQKV];   // (B*S, 3D): q | k | v
__device__ float g_attn[(size_t)MROWS * DD];    // (B,S,H,HD) == (B*S, D)

__device__ __forceinline__ uint32_t f2tf32(float f) {
    uint32_t u;
    asm("cvt.rna.tf32.f32 %0, %1;" : "=r"(u) : "f"(f));
    return u;
}

// ---------------------------------------------------------------------------
// TF32 tensor-core GEMM: C[M,N] = A[M,K] @ B[K,N]
// 128x128 block tile, BK=32, 8 warps (2m x 4n), warp tile 64x32,
// per warp 4x4 fragments of mma.sync.m16n8k8 (tf32 -> fp32 accum).
// Smem strides chosen so all fragment LDS are bank-conflict-free:
//   A stride 36: bank = (4r + c) mod 32, bijective over the warp
//   B stride 136: bank = (8c + n) mod 32, bijective over the warp
// OUTPROJ=false: A = param (x), C = g_qkv
// OUTPROJ=true : A = g_attn,    C = param (d_out)
// ---------------------------------------------------------------------------
template <bool OUTPROJ>
__global__ __launch_bounds__(256)
void mma_gemm(int M_, int N_, int K_,
              const float* __restrict__ Ap,
              const float* __restrict__ Bm,
              float* __restrict__ Cp)
{
    const float* A = OUTPROJ ? (const float*)g_attn : Ap;
    float* C = OUTPROJ ? Cp : (float*)g_qkv;

    __shared__ uint32_t As[128][36];   // [m][k], tf32 bits
    __shared__ uint32_t Bs[32][136];   // [k][n], tf32 bits

    const int tid  = threadIdx.x;
    const int warp = tid >> 5;
    const int lane = tid & 31;
    const int r = lane >> 2;           // 0..7
    const int c = lane & 3;            // 0..3

    const int bm = blockIdx.y * 128;
    const int bn = blockIdx.x * 128;
    const int wm = (warp >> 2) * 64;   // warp row offset within block
    const int wn = (warp & 3) * 32;    // warp col offset within block

    float acc[4][4][4] = {};

    for (int k0 = 0; k0 < K_; k0 += 32) {
        // --- Load A tile 128x32 (1024 float4 / 256 thr = 4 each) ---
        #pragma unroll
        for (int p = 0; p < 4; p++) {
            int f4 = tid + p * 256;
            int rr = f4 >> 3;
            int cc = (f4 & 7) << 2;
            float4 v = *reinterpret_cast<const float4*>(
                A + (size_t)(bm + rr) * K_ + k0 + cc);
            uint4 t = make_uint4(f2tf32(v.x), f2tf32(v.y), f2tf32(v.z), f2tf32(v.w));
            *reinterpret_cast<uint4*>(&As[rr][cc]) = t;
        }
        // --- Load B tile 32x128 ---
        #pragma unroll
        for (int p = 0; p < 4; p++) {
            int f4 = tid + p * 256;
            int rr = f4 >> 5;
            int cc = (f4 & 31) << 2;
            float4 v = *reinterpret_cast<const float4*>(
                Bm + (size_t)(k0 + rr) * N_ + bn + cc);
            uint4 t = make_uint4(f2tf32(v.x), f2tf32(v.y), f2tf32(v.z), f2tf32(v.w));
            *reinterpret_cast<uint4*>(&Bs[rr][cc]) = t;
        }
        __syncthreads();

        // --- 4 k-steps of 8 ---
        #pragma unroll
        for (int ks = 0; ks < 4; ks++) {
            const int kk = ks * 8;
            uint32_t af[4][4], bf[4][2];
            #pragma unroll
            for (int mi = 0; mi < 4; mi++) {
                int row = wm + mi * 16 + r;
                af[mi][0] = As[row][kk + c];
                af[mi][1] = As[row + 8][kk + c];
                af[mi][2] = As[row][kk + c + 4];
                af[mi][3] = As[row + 8][kk + c + 4];
            }
            #pragma unroll
            for (int ni = 0; ni < 4; ni++) {
                int col = wn + ni * 8 + r;
                bf[ni][0] = Bs[kk + c][col];
                bf[ni][1] = Bs[kk + c + 4][col];
            }
            #pragma unroll
            for (int mi = 0; mi < 4; mi++)
                #pragma unroll
                for (int ni = 0; ni < 4; ni++) {
                    asm volatile(
                        "mma.sync.aligned.m16n8k8.row.col.f32.tf32.tf32.f32 "
                        "{%0,%1,%2,%3}, {%4,%5,%6,%7}, {%8,%9}, {%0,%1,%2,%3};"
                        : "+f"(acc[mi][ni][0]), "+f"(acc[mi][ni][1]),
                          "+f"(acc[mi][ni][2]), "+f"(acc[mi][ni][3])
                        : "r"(af[mi][0]), "r"(af[mi][1]),
                          "r"(af[mi][2]), "r"(af[mi][3]),
                          "r"(bf[ni][0]), "r"(bf[ni][1]));
                }
        }
        __syncthreads();
    }

    // --- Epilogue: c0,c1 at (row, 2c), c2,c3 at (row+8, 2c) ---
    #pragma unroll
    for (int mi = 0; mi < 4; mi++) {
        int row0 = bm + wm + mi * 16 + r;
        #pragma unroll
        for (int ni = 0; ni < 4; ni++) {
            int col = bn + wn + ni * 8 + c * 2;
            *reinterpret_cast<float2*>(C + (size_t)row0 * N_ + col) =
                make_float2(acc[mi][ni][0], acc[mi][ni][1]);
            *reinterpret_cast<float2*>(C + (size_t)(row0 + 8) * N_ + col) =
                make_float2(acc[mi][ni][2], acc[mi][ni][3]);
        }
    }
}

// ---------------------------------------------------------------------------
// Causal flash attention (unchanged from R0 — pure fp32, rel_err anchor).
// ---------------------------------------------------------------------------
__global__ __launch_bounds__(256)
void attn64(void)
{
    __shared__ float Qs[64][64];
    __shared__ float KPs[64][64];
    __shared__ float Vs[64][64];

    const int tid = threadIdx.x;
    const int w = tid >> 5;
    const int l = tid & 31;
    const int qt = blockIdx.x;
    const int h  = blockIdx.y;
    const int b  = blockIdx.z;
    const int ldq = NQKV;

    const float* qkv = g_qkv;
    const float* qbase = qkv + ((size_t)b * SS + (size_t)qt * 64) * ldq + h * HDIM;
    const float* kb0   = qkv + (size_t)b * SS * ldq + DD + h * HDIM;
    const float* vb0   = qkv + (size_t)b * SS * ldq + 2 * DD + h * HDIM;

    for (int idx = tid; idx < 64 * 16; idx += 256) {
        int r = idx >> 4;
        int c = (idx & 15) << 2;
        float4 v = *reinterpret_cast<const float4*>(qbase + (size_t)r * ldq + c);
        Qs[r][c + 0] = v.x * 0.125f;
        Qs[r][c + 1] = v.y * 0.125f;
        Qs[r][c + 2] = v.z * 0.125f;
        Qs[r][c + 3] = v.w * 0.125f;
    }

    float o0[8] = {}, o1[8] = {};
    float mrow[8], lrow[8];
    #pragma unroll
    for (int i = 0; i < 8; i++) { mrow[i] = -CUDART_INF_F; lrow[i] = 0.f; }

    for (int kt = 0; kt <= qt; kt++) {
        __syncthreads();

        const float* kb = kb0 + (size_t)kt * 64 * ldq;
        const float* vb = vb0 + (size_t)kt * 64 * ldq;

        for (int idx = tid; idx < 64 * 16; idx += 256) {
            int r = idx & 63;
            int c = (idx >> 6) << 2;
            float4 kv = *reinterpret_cast<const float4*>(kb + (size_t)r * ldq + c);
            KPs[c + 0][r] = kv.x;
            KPs[c + 1][r] = kv.y;
            KPs[c + 2][r] = kv.z;
            KPs[c + 3][r] = kv.w;
        }
        for (int idx = tid; idx < 64 * 16; idx += 256) {
            int r = idx >> 4;
            int c = (idx & 15) << 2;
            *reinterpret_cast<float4*>(&Vs[r][c]) =
                *reinterpret_cast<const float4*>(vb + (size_t)r * ldq + c);
        }
        __syncthreads();

        float s0[8] = {}, s1[8] = {};
        #pragma unroll 8
        for (int d = 0; d < 64; d++) {
            float k0v = KPs[d][l];
            float k1v = KPs[d][l + 32];
            #pragma unroll
            for (int i = 0; i < 8; i++) {
                float q = Qs[w * 8 + i][d];
                s0[i] = fmaf(q, k0v, s0[i]);
                s1[i] = fmaf(q, k1v, s1[i]);
            }
        }

        if (kt == qt) {
            #pragma unroll
            for (int i = 0; i < 8; i++) {
                int rl = w * 8 + i;
                if (l > rl)      s0[i] = -CUDART_INF_F;
                if (l + 32 > rl) s1[i] = -CUDART_INF_F;
            }
        }

        __syncthreads();

        #pragma unroll
        for (int i = 0; i < 8; i++) {
            float mx = fmaxf(s0[i], s1[i]);
            #pragma unroll
            for (int off = 16; off; off >>= 1)
                mx = fmaxf(mx, __shfl_xor_sync(0xffffffffu, mx, off));
            float mnew = fmaxf(mrow[i], mx);
            float corr = __expf(mrow[i] - mnew);
            float p0 = __expf(s0[i] - mnew);
            float p1 = __expf(s1[i] - mnew);
            float rs = p0 + p1;
            #pragma unroll
            for (int off = 16; off; off >>= 1)
                rs += __shfl_xor_sync(0xffffffffu, rs, off);
            lrow[i] = lrow[i] * corr + rs;
            mrow[i] = mnew;
            o0[i] *= corr;
            o1[i] *= corr;
            KPs[w * 8 + i][l]      = p0;
            KPs[w * 8 + i][l + 32] = p1;
        }
        __syncwarp();

        #pragma unroll 8
        for (int kc = 0; kc < 64; kc++) {
            float v0 = Vs[kc][l];
            float v1 = Vs[kc][l + 32];
            #pragma unroll
            for (int i = 0; i < 8; i++) {
                float p = KPs[w * 8 + i][kc];
                o0[i] = fmaf(p, v0, o0[i]);
                o1[i] = fmaf(p, v1, o1[i]);
            }
        }
    }

    float* ob = g_attn + ((size_t)b * SS + (size_t)qt * 64) * DD + h * HDIM;
    #pragma unroll
    for (int i = 0; i < 8; i++) {
        float inv = 1.0f / lrow[i];
        ob[(size_t)(w * 8 + i) * DD + l]      = o0[i] * inv;
        ob[(size_t)(w * 8 + i) * DD + l + 32] = o1[i] * inv;
    }
}

// ---------------------------------------------------------------------------
extern "C" void kernel_launch(void* const* d_in, const int* in_sizes, int n_in,
                              void* d_out, int out_size)
{
    const float* x    = (const float*)d_in[0];  // (2,2048,1024)
    const float* wqkv = (const float*)d_in[1];  // (1024,3072)
    const float* wout = (const float*)d_in[2];  // (1024,1024)
    float* out = (float*)d_out;                 // (2,2048,1024)

    // 1) QKV projection: (4096,1024) @ (1024,3072) -> g_qkv  [tf32 MMA]
    mma_gemm<false><<<dim3(NQKV / 128, MROWS / 128), 256>>>(
        MROWS, NQKV, DD, x, wqkv, nullptr);

    // 2) Causal attention per (b, h, qtile) -> g_attn  [fp32]
    attn64<<<dim3(SS / 64, HH, BB), 256>>>();

    // 3) Output projection: (4096,1024) @ (1024,1024) -> d_out  [tf32 MMA]
    mma_gemm<true><<<dim3(DD / 128, MROWS / 128), 256>>>(
        MROWS, DD, DD, nullptr, wout, out);
}

// round 3
// speedup vs baseline: 3.3239x; 2.1129x over previous
#include <cuda_runtime.h>
#include <math_constants.h>
#include <stdint.h>

// Problem constants
#define BB 2
#define SS 2048
#define DD 1024
#define HH 16
#define HDIM 64
#define MROWS (BB * SS)      // 4096
#define NQKV (3 * DD)        // 3072

// Scratch (allocation-free rule: __device__ globals)
__device__ float g_qkv[(size_t)MROWS * NQKV];   // (B*S, 3D): q | k | v
__device__ float g_attn[(size_t)MROWS * DD];    // (B,S,H,HD) == (B*S, D)

__device__ __forceinline__ uint32_t f2tf32(float f) {
    uint32_t u;
    asm("cvt.rna.tf32.f32 %0, %1;" : "=r"(u) : "f"(f));
    return u;
}

__device__ __forceinline__ void mma_tf32(float d[4],
                                         uint32_t a0, uint32_t a1, uint32_t a2, uint32_t a3,
                                         uint32_t b0, uint32_t b1) {
    asm volatile(
        "mma.sync.aligned.m16n8k8.row.col.f32.tf32.tf32.f32 "
        "{%0,%1,%2,%3}, {%4,%5,%6,%7}, {%8,%9}, {%0,%1,%2,%3};"
        : "+f"(d[0]), "+f"(d[1]), "+f"(d[2]), "+f"(d[3])
        : "r"(a0), "r"(a1), "r"(a2), "r"(a3), "r"(b0), "r"(b1));
}

// ---------------------------------------------------------------------------
// TF32 tensor-core GEMM (unchanged from R1): C[M,N] = A[M,K] @ B[K,N]
// ---------------------------------------------------------------------------
template <bool OUTPROJ>
__global__ __launch_bounds__(256)
void mma_gemm(int M_, int N_, int K_,
              const float* __restrict__ Ap,
              const float* __restrict__ Bm,
              float* __restrict__ Cp)
{
    const float* A = OUTPROJ ? (const float*)g_attn : Ap;
    float* C = OUTPROJ ? Cp : (float*)g_qkv;

    __shared__ uint32_t As[128][36];
    __shared__ uint32_t Bs[32][136];

    const int tid  = threadIdx.x;
    const int warp = tid >> 5;
    const int lane = tid & 31;
    const int r = lane >> 2;
    const int c = lane & 3;

    const int bm = blockIdx.y * 128;
    const int bn = blockIdx.x * 128;
    const int wm = (warp >> 2) * 64;
    const int wn = (warp & 3) * 32;

    float acc[4][4][4] = {};

    for (int k0 = 0; k0 < K_; k0 += 32) {
        #pragma unroll
        for (int p = 0; p < 4; p++) {
            int f4 = tid + p * 256;
            int rr = f4 >> 3;
            int cc = (f4 & 7) << 2;
            float4 v = *reinterpret_cast<const float4*>(
                A + (size_t)(bm + rr) * K_ + k0 + cc);
            uint4 t = make_uint4(f2tf32(v.x), f2tf32(v.y), f2tf32(v.z), f2tf32(v.w));
            *reinterpret_cast<uint4*>(&As[rr][cc]) = t;
        }
        #pragma unroll
        for (int p = 0; p < 4; p++) {
            int f4 = tid + p * 256;
            int rr = f4 >> 5;
            int cc = (f4 & 31) << 2;
            float4 v = *reinterpret_cast<const float4*>(
                Bm + (size_t)(k0 + rr) * N_ + bn + cc);
            uint4 t = make_uint4(f2tf32(v.x), f2tf32(v.y), f2tf32(v.z), f2tf32(v.w));
            *reinterpret_cast<uint4*>(&Bs[rr][cc]) = t;
        }
        __syncthreads();

        #pragma unroll
        for (int ks = 0; ks < 4; ks++) {
            const int kk = ks * 8;
            uint32_t af[4][4], bf[4][2];
            #pragma unroll
            for (int mi = 0; mi < 4; mi++) {
                int row = wm + mi * 16 + r;
                af[mi][0] = As[row][kk + c];
                af[mi][1] = As[row + 8][kk + c];
                af[mi][2] = As[row][kk + c + 4];
                af[mi][3] = As[row + 8][kk + c + 4];
            }
            #pragma unroll
            for (int ni = 0; ni < 4; ni++) {
                int col = wn + ni * 8 + r;
                bf[ni][0] = Bs[kk + c][col];
                bf[ni][1] = Bs[kk + c + 4][col];
            }
            #pragma unroll
            for (int mi = 0; mi < 4; mi++)
                #pragma unroll
                for (int ni = 0; ni < 4; ni++)
                    mma_tf32(acc[mi][ni], af[mi][0], af[mi][1], af[mi][2], af[mi][3],
                             bf[ni][0], bf[ni][1]);
        }
        __syncthreads();
    }

    #pragma unroll
    for (int mi = 0; mi < 4; mi++) {
        int row0 = bm + wm + mi * 16 + r;
        #pragma unroll
        for (int ni = 0; ni < 4; ni++) {
            int col = bn + wn + ni * 8 + c * 2;
            *reinterpret_cast<float2*>(C + (size_t)row0 * N_ + col) =
                make_float2(acc[mi][ni][0], acc[mi][ni][1]);
            *reinterpret_cast<float2*>(C + (size_t)(row0 + 8) * N_ + col) =
                make_float2(acc[mi][ni][2], acc[mi][ni][3]);
        }
    }
}

// ---------------------------------------------------------------------------
// TF32 tensor-core causal flash attention.
// Block = (b, h, 64-row query tile), 128 threads = 4 warps.
// Warp w owns query rows [16w, 16w+16); full 64-key tile width per warp.
// Smem: KPs (K^T bits, then P bits, stride 68) + Vs (stride 72).
// Bank-bijection proofs:
//   K b-frag: addr = key*68 + d, lanes (lr=l>>2 -> key, lc=l&3 -> d): bank=4*lr+lc
//   V b-frag: addr = key*72 + d, lanes (lc -> key, lr -> d):          bank=8*lc+lr
//   P a-frag: addr = row*68 + k, lanes (lr -> row, lc -> k):          bank=4*lr+lc
// ---------------------------------------------------------------------------
#define KST 68
#define VST 72

__global__ __launch_bounds__(128)
void attn_mma(void)
{
    __shared__ uint32_t KPs[64 * KST];   // K^T tile, later P tile (tf32 bits)
    __shared__ uint32_t Vs[64 * VST];    // V tile (tf32 bits)

    const int tid = threadIdx.x;
    const int w  = tid >> 5;
    const int l  = tid & 31;
    const int lr = l >> 2;               // 0..7
    const int lc = l & 3;                // 0..3
    const int qt = gridDim.x - 1 - blockIdx.x;  // long blocks first
    const int h  = blockIdx.y;
    const int b  = blockIdx.z;
    const int ldq = NQKV;

    const float* qb  = g_qkv + ((size_t)b * SS + (size_t)qt * 64) * ldq + h * HDIM;
    const float* kb0 = g_qkv + (size_t)b * SS * ldq + DD + h * HDIM;
    const float* vb0 = g_qkv + (size_t)b * SS * ldq + 2 * DD + h * HDIM;

    // Q fragments held in registers for the whole block (pre-scaled by 1/8)
    uint32_t qf[8][4];
    {
        const float* q0 = qb + (size_t)(w * 16 + lr) * ldq;
        const float* q1 = q0 + (size_t)8 * ldq;
        #pragma unroll
        for (int ks = 0; ks < 8; ks++) {
            qf[ks][0] = f2tf32(q0[ks * 8 + lc] * 0.125f);
            qf[ks][1] = f2tf32(q1[ks * 8 + lc] * 0.125f);
            qf[ks][2] = f2tf32(q0[ks * 8 + lc + 4] * 0.125f);
            qf[ks][3] = f2tf32(q1[ks * 8 + lc + 4] * 0.125f);
        }
    }

    float o[8][4] = {};
    float mA = -CUDART_INF_F, mB = -CUDART_INF_F;
    float lA = 0.f, lB = 0.f;

    for (int kt = 0; kt <= qt; kt++) {
        __syncthreads();   // previous iteration's KPs(P)/Vs readers done

        const float* kb = kb0 + (size_t)kt * 64 * ldq;
        const float* vb = vb0 + (size_t)kt * 64 * ldq;

        // Load K and V tiles (64x64 each), convert to tf32 bits
        #pragma unroll
        for (int p = 0; p < 8; p++) {
            int f4 = tid + p * 128;
            int r  = f4 >> 4;
            int c4 = (f4 & 15) << 2;
            float4 kv = *reinterpret_cast<const float4*>(kb + (size_t)r * ldq + c4);
            *reinterpret_cast<uint4*>(&KPs[r * KST + c4]) =
                make_uint4(f2tf32(kv.x), f2tf32(kv.y), f2tf32(kv.z), f2tf32(kv.w));
            float4 vv = *reinterpret_cast<const float4*>(vb + (size_t)r * ldq + c4);
            *reinterpret_cast<uint4*>(&Vs[r * VST + c4]) =
                make_uint4(f2tf32(vv.x), f2tf32(vv.y), f2tf32(vv.z), f2tf32(vv.w));
        }
        __syncthreads();

        // ---- S = Q @ K^T : per warp 16 rows x 64 keys ----
        float s[8][4] = {};
        #pragma unroll
        for (int ks = 0; ks < 8; ks++) {
            const int kk = ks * 8;
            #pragma unroll
            for (int ni = 0; ni < 8; ni++) {
                uint32_t b0 = KPs[(ni * 8 + lr) * KST + kk + lc];
                uint32_t b1 = KPs[(ni * 8 + lr) * KST + kk + lc + 4];
                mma_tf32(s[ni], qf[ks][0], qf[ks][1], qf[ks][2], qf[ks][3], b0, b1);
            }
        }

        // Causal mask on diagonal tile (rowA = 16w+lr, rowB = rowA+8; local cols)
        if (kt == qt) {
            const int rowA = w * 16 + lr;
            const int rowB = rowA + 8;
            #pragma unroll
            for (int ni = 0; ni < 8; ni++) {
                int c0 = ni * 8 + 2 * lc;
                int c1 = c0 + 1;
                if (c0 > rowA) s[ni][0] = -CUDART_INF_F;
                if (c1 > rowA) s[ni][1] = -CUDART_INF_F;
                if (c0 > rowB) s[ni][2] = -CUDART_INF_F;
                if (c1 > rowB) s[ni][3] = -CUDART_INF_F;
            }
        }

        __syncthreads();   // all warps done reading KPs as K -> reuse as P

        // ---- online softmax (fp32) ----
        float mxA = -CUDART_INF_F, mxB = -CUDART_INF_F;
        #pragma unroll
        for (int ni = 0; ni < 8; ni++) {
            mxA = fmaxf(mxA, fmaxf(s[ni][0], s[ni][1]));
            mxB = fmaxf(mxB, fmaxf(s[ni][2], s[ni][3]));
        }
        #pragma unroll
        for (int off = 1; off <= 2; off <<= 1) {
            mxA = fmaxf(mxA, __shfl_xor_sync(0xffffffffu, mxA, off));
            mxB = fmaxf(mxB, __shfl_xor_sync(0xffffffffu, mxB, off));
        }
        const float mnA = fmaxf(mA, mxA);
        const float mnB = fmaxf(mB, mxB);
        const float cA = __expf(mA - mnA);
        const float cB = __expf(mB - mnB);

        float rsA = 0.f, rsB = 0.f;
        const int rA = (w * 16 + lr) * KST;
        const int rB = rA + 8 * KST;
        #pragma unroll
        for (int ni = 0; ni < 8; ni++) {
            float p0 = __expf(s[ni][0] - mnA);
            float p1 = __expf(s[ni][1] - mnA);
            float p2 = __expf(s[ni][2] - mnB);
            float p3 = __expf(s[ni][3] - mnB);
            rsA += p0 + p1;
            rsB += p2 + p3;
            int col = ni * 8 + 2 * lc;
            *reinterpret_cast<uint2*>(&KPs[rA + col]) = make_uint2(f2tf32(p0), f2tf32(p1));
            *reinterpret_cast<uint2*>(&KPs[rB + col]) = make_uint2(f2tf32(p2), f2tf32(p3));
        }
        #pragma unroll
        for (int off = 1; off <= 2; off <<= 1) {
            rsA += __shfl_xor_sync(0xffffffffu, rsA, off);
            rsB += __shfl_xor_sync(0xffffffffu, rsB, off);
        }
        lA = lA * cA + rsA;  mA = mnA;
        lB = lB * cB + rsB;  mB = mnB;
        #pragma unroll
        for (int ni = 0; ni < 8; ni++) {
            o[ni][0] *= cA;  o[ni][1] *= cA;
            o[ni][2] *= cB;  o[ni][3] *= cB;
        }
        __syncwarp();   // P rows written+read by this warp only

        // ---- O += P @ V ----
        #pragma unroll
        for (int ks = 0; ks < 8; ks++) {
            const int kk = ks * 8;
            uint32_t a0 = KPs[rA + kk + lc];
            uint32_t a1 = KPs[rB + kk + lc];
            uint32_t a2 = KPs[rA + kk + lc + 4];
            uint32_t a3 = KPs[rB + kk + lc + 4];
            #pragma unroll
            for (int ni = 0; ni < 8; ni++) {
                uint32_t b0 = Vs[(kk + lc) * VST + ni * 8 + lr];
                uint32_t b1 = Vs[(kk + lc + 4) * VST + ni * 8 + lr];
                mma_tf32(o[ni], a0, a1, a2, a3, b0, b1);
            }
        }
    }

    // Epilogue: normalize and write (B,S,H,HD) == (B*S, D)
    const float iA = 1.0f / lA;
    const float iB = 1.0f / lB;
    float* obA = g_attn + ((size_t)b * SS + (size_t)qt * 64 + w * 16 + lr) * DD + h * HDIM;
    float* obB = obA + (size_t)8 * DD;
    #pragma unroll
    for (int ni = 0; ni < 8; ni++) {
        int col = ni * 8 + 2 * lc;
        *reinterpret_cast<float2*>(obA + col) = make_float2(o[ni][0] * iA, o[ni][1] * iA);
        *reinterpret_cast<float2*>(obB + col) = make_float2(o[ni][2] * iB, o[ni][3] * iB);
    }
}

// ---------------------------------------------------------------------------
extern "C" void kernel_launch(void* const* d_in, const int* in_sizes, int n_in,
                              void* d_out, int out_size)
{
    const float* x    = (const float*)d_in[0];  // (2,2048,1024)
    const float* wqkv = (const float*)d_in[1];  // (1024,3072)
    const float* wout = (const float*)d_in[2];  // (1024,1024)
    float* out = (float*)d_out;                 // (2,2048,1024)

    // 1) QKV projection: (4096,1024) @ (1024,3072) -> g_qkv  [tf32 MMA]
    mma_gemm<false><<<dim3(NQKV / 128, MROWS / 128), 256>>>(
        MROWS, NQKV, DD, x, wqkv, nullptr);

    // 2) Causal attention -> g_attn  [tf32 MMA + fp32 softmax]
    attn_mma<<<dim3(SS / 64, HH, BB), 128>>>();

    // 3) Output projection: (4096,1024) @ (1024,1024) -> d_out  [tf32 MMA]
    mma_gemm<true><<<dim3(DD / 128, MROWS / 128), 256>>>(
        MROWS, DD, DD, nullptr, wout, out);
}

// round 4
// speedup vs baseline: 3.9091x; 1.1760x over previous
#include <cuda_runtime.h>
#include <math_constants.h>
#include <stdint.h>

// Problem constants
#define BB 2
#define SS 2048
#define DD 1024
#define HH 16
#define HDIM 64
#define MROWS (BB * SS)      // 4096
#define NQKV (3 * DD)        // 3072

// Scratch (allocation-free rule: __device__ globals)
__device__ float g_qkv[(size_t)MROWS * NQKV];   // (B*S, 3D): q | k | v (tf32-rounded)
__device__ float g_attn[(size_t)MROWS * DD];    // (B,S,H,HD) == (B*S,D) (tf32-rounded)
__device__ float g_xr[(size_t)MROWS * DD];      // tf32-rounded x
__device__ float g_wqkvr[(size_t)DD * NQKV];    // tf32-rounded w_qkv
__device__ float g_woutr[(size_t)DD * DD];      // tf32-rounded w_out

__device__ __forceinline__ uint32_t f2tf32(float f) {
    uint32_t u;
    asm("cvt.rna.tf32.f32 %0, %1;" : "=r"(u) : "f"(f));
    return u;
}

__device__ __forceinline__ void mma_tf32(float d[4],
                                         uint32_t a0, uint32_t a1, uint32_t a2, uint32_t a3,
                                         uint32_t b0, uint32_t b1) {
    asm volatile(
        "mma.sync.aligned.m16n8k8.row.col.f32.tf32.tf32.f32 "
        "{%0,%1,%2,%3}, {%4,%5,%6,%7}, {%8,%9}, {%0,%1,%2,%3};"
        : "+f"(d[0]), "+f"(d[1]), "+f"(d[2]), "+f"(d[3])
        : "r"(a0), "r"(a1), "r"(a2), "r"(a3), "r"(b0), "r"(b1));
}

__device__ __forceinline__ void cp16(uint32_t dst_smem, const void* src) {
    asm volatile("cp.async.cg.shared.global [%0], [%1], 16;"
                 :: "r"(dst_smem), "l"(src));
}
__device__ __forceinline__ void cp_commit() {
    asm volatile("cp.async.commit_group;" ::: "memory");
}
__device__ __forceinline__ void cp_wait(int pending) {
    if (pending) asm volatile("cp.async.wait_group 1;" ::: "memory");
    else         asm volatile("cp.async.wait_group 0;" ::: "memory");
}

// ---------------------------------------------------------------------------
// Pre-round inputs to tf32 (one pass; values then flow bit-exactly into MMA)
// ---------------------------------------------------------------------------
__global__ __launch_bounds__(256)
void pre_round(const float4* __restrict__ x,
               const float4* __restrict__ wq,
               const float4* __restrict__ wo)
{
    const int NX = (MROWS * DD) / 4;        // 1048576
    const int NQ = (DD * NQKV) / 4;         // 786432
    const int NO = (DD * DD) / 4;           // 262144
    for (int i = blockIdx.x * blockDim.x + threadIdx.x;
         i < NX + NQ + NO; i += gridDim.x * blockDim.x) {
        float4 v; float4* dst;
        if (i < NX)           { v = x[i];            dst = (float4*)g_xr + i; }
        else if (i < NX + NQ) { v = wq[i - NX];      dst = (float4*)g_wqkvr + (i - NX); }
        else                  { v = wo[i - NX - NQ]; dst = (float4*)g_woutr + (i - NX - NQ); }
        uint4 t = make_uint4(f2tf32(v.x), f2tf32(v.y), f2tf32(v.z), f2tf32(v.w));
        *dst = *reinterpret_cast<float4*>(&t);
    }
}

// ---------------------------------------------------------------------------
// TF32 tensor-core GEMM, cp.async double-buffered.
// 128x128 block tile, BK=32, 8 warps (2m x 4n), warp tile 64x32.
// Dynamic smem: As[2][128*36] then Bs[2][32*136]  (71680 B).
// MODE 0: A=g_xr,  B=g_wqkvr, C=g_qkv (epilogue tf32-rounds)
// MODE 1: A=g_attn, B=g_woutr, C=Cp   (fp32 output, no rounding)
// ---------------------------------------------------------------------------
#define ASZ (128 * 36)
#define BSZ (32 * 136)

template <int MODE>
__global__ __launch_bounds__(256, 2)
void mma_gemm(int M_, int N_, int K_, float* __restrict__ Cp)
{
    extern __shared__ uint32_t dynsmem[];
    const float* A = (MODE == 0) ? (const float*)g_xr    : (const float*)g_attn;
    const float* Bm = (MODE == 0) ? (const float*)g_wqkvr : (const float*)g_woutr;
    float* C = (MODE == 0) ? (float*)g_qkv : Cp;

    const int tid  = threadIdx.x;
    const int warp = tid >> 5;
    const int lane = tid & 31;
    const int r = lane >> 2;
    const int c = lane & 3;

    const int bm = blockIdx.y * 128;
    const int bn = blockIdx.x * 128;
    const int wm = (warp >> 2) * 64;
    const int wn = (warp & 3) * 32;

    const uint32_t smem_base = (uint32_t)__cvta_generic_to_shared(dynsmem);

    float acc[4][4][4] = {};
    const int nk = K_ >> 5;

    // tile loader: stage st, k offset k0
    auto load_tiles = [&](int st, int k0) {
        uint32_t abase = smem_base + (uint32_t)(st * ASZ) * 4u;
        uint32_t bbase = smem_base + (uint32_t)(2 * ASZ + st * BSZ) * 4u;
        #pragma unroll
        for (int p = 0; p < 4; p++) {
            int f4 = tid + p * 256;
            int rr = f4 >> 3;
            int cc = (f4 & 7) << 2;
            cp16(abase + (uint32_t)(rr * 36 + cc) * 4u,
                 A + (size_t)(bm + rr) * K_ + k0 + cc);
        }
        #pragma unroll
        for (int p = 0; p < 4; p++) {
            int f4 = tid + p * 256;
            int rr = f4 >> 5;
            int cc = (f4 & 31) << 2;
            cp16(bbase + (uint32_t)(rr * 136 + cc) * 4u,
                 Bm + (size_t)(k0 + rr) * N_ + bn + cc);
        }
        cp_commit();
    };

    load_tiles(0, 0);

    for (int i = 0; i < nk; i++) {
        const int st = i & 1;
        const int has_next = (i + 1 < nk);
        if (has_next) load_tiles(st ^ 1, (i + 1) << 5);
        cp_wait(has_next);
        __syncthreads();

        const uint32_t* Asb = dynsmem + st * ASZ;
        const uint32_t* Bsb = dynsmem + 2 * ASZ + st * BSZ;

        #pragma unroll
        for (int ks = 0; ks < 4; ks++) {
            const int kk = ks * 8;
            uint32_t af[4][4], bf[4][2];
            #pragma unroll
            for (int mi = 0; mi < 4; mi++) {
                int row = wm + mi * 16 + r;
                af[mi][0] = Asb[row * 36 + kk + c];
                af[mi][1] = Asb[(row + 8) * 36 + kk + c];
                af[mi][2] = Asb[row * 36 + kk + c + 4];
                af[mi][3] = Asb[(row + 8) * 36 + kk + c + 4];
            }
            #pragma unroll
            for (int ni = 0; ni < 4; ni++) {
                int col = wn + ni * 8 + r;
                bf[ni][0] = Bsb[(kk + c) * 136 + col];
                bf[ni][1] = Bsb[(kk + c + 4) * 136 + col];
            }
            #pragma unroll
            for (int mi = 0; mi < 4; mi++)
                #pragma unroll
                for (int ni = 0; ni < 4; ni++)
                    mma_tf32(acc[mi][ni], af[mi][0], af[mi][1], af[mi][2], af[mi][3],
                             bf[ni][0], bf[ni][1]);
        }
        __syncthreads();
    }

    #pragma unroll
    for (int mi = 0; mi < 4; mi++) {
        int row0 = bm + wm + mi * 16 + r;
        #pragma unroll
        for (int ni = 0; ni < 4; ni++) {
            int col = bn + wn + ni * 8 + c * 2;
            if (MODE == 0) {
                uint2 v0 = make_uint2(f2tf32(acc[mi][ni][0]), f2tf32(acc[mi][ni][1]));
                uint2 v1 = make_uint2(f2tf32(acc[mi][ni][2]), f2tf32(acc[mi][ni][3]));
                *reinterpret_cast<uint2*>(C + (size_t)row0 * N_ + col) = v0;
                *reinterpret_cast<uint2*>(C + (size_t)(row0 + 8) * N_ + col) = v1;
            } else {
                *reinterpret_cast<float2*>(C + (size_t)row0 * N_ + col) =
                    make_float2(acc[mi][ni][0], acc[mi][ni][1]);
                *reinterpret_cast<float2*>(C + (size_t)(row0 + 8) * N_ + col) =
                    make_float2(acc[mi][ni][2], acc[mi][ni][3]);
            }
        }
    }
}

// ---------------------------------------------------------------------------
// TF32 tensor-core causal flash attention, cp.async double-buffered K/V.
// Block = (b, h, 64-row qtile), 128 threads = 4 warps; warp owns 16 q-rows.
// Dynamic smem: KP[2][64*68] (K tile then P tile) + V[2][64*72]  (71680 B).
// g_qkv is tf32-rounded, so no cvt needed on the async path.
// ---------------------------------------------------------------------------
#define KST 68
#define VST 72
#define KPSZ (64 * KST)
#define VSZ  (64 * VST)

__global__ __launch_bounds__(128, 3)
void attn_mma(void)
{
    extern __shared__ uint32_t dynsmem[];

    const int tid = threadIdx.x;
    const int w  = tid >> 5;
    const int l  = tid & 31;
    const int lr = l >> 2;
    const int lc = l & 3;
    const int qt = gridDim.x - 1 - blockIdx.x;   // long blocks first
    const int h  = blockIdx.y;
    const int b  = blockIdx.z;
    const int ldq = NQKV;

    const float* qb  = g_qkv + ((size_t)b * SS + (size_t)qt * 64) * ldq + h * HDIM;
    const float* kb0 = g_qkv + (size_t)b * SS * ldq + DD + h * HDIM;
    const float* vb0 = g_qkv + (size_t)b * SS * ldq + 2 * DD + h * HDIM;

    const uint32_t smem_base = (uint32_t)__cvta_generic_to_shared(dynsmem);

    // issue K+V tile loads for key-tile kt into stage st
    auto load_kv = [&](int st, int kt) {
        const float* kb = kb0 + (size_t)kt * 64 * ldq;
        const float* vb = vb0 + (size_t)kt * 64 * ldq;
        uint32_t kbase = smem_base + (uint32_t)(st * KPSZ) * 4u;
        uint32_t vbase = smem_base + (uint32_t)(2 * KPSZ + st * VSZ) * 4u;
        #pragma unroll
        for (int p = 0; p < 8; p++) {
            int f4 = tid + p * 128;
            int r  = f4 >> 4;
            int c4 = (f4 & 15) << 2;
            cp16(kbase + (uint32_t)(r * KST + c4) * 4u, kb + (size_t)r * ldq + c4);
            cp16(vbase + (uint32_t)(r * VST + c4) * 4u, vb + (size_t)r * ldq + c4);
        }
        cp_commit();
    };

    // Q fragments in registers (values already tf32; *0.125 exact, cvt idempotent)
    uint32_t qf[8][4];
    {
        const float* q0 = qb + (size_t)(w * 16 + lr) * ldq;
        const float* q1 = q0 + (size_t)8 * ldq;
        #pragma unroll
        for (int ks = 0; ks < 8; ks++) {
            qf[ks][0] = f2tf32(q0[ks * 8 + lc] * 0.125f);
            qf[ks][1] = f2tf32(q1[ks * 8 + lc] * 0.125f);
            qf[ks][2] = f2tf32(q0[ks * 8 + lc + 4] * 0.125f);
            qf[ks][3] = f2tf32(q1[ks * 8 + lc + 4] * 0.125f);
        }
    }

    load_kv(0, 0);

    float o[8][4] = {};
    float mA = -CUDART_INF_F, mB = -CUDART_INF_F;
    float lA = 0.f, lB = 0.f;

    for (int kt = 0; kt <= qt; kt++) {
        const int cur = kt & 1;
        __syncthreads();                       // buf[cur^1] free (kt-1 PV done)
        const int has_next = (kt < qt);
        if (has_next) load_kv(cur ^ 1, kt + 1);
        cp_wait(has_next);
        __syncthreads();                       // K/V(kt) visible to all warps

        const uint32_t* KPb = dynsmem + cur * KPSZ;
        const uint32_t* Vsb = dynsmem + 2 * KPSZ + cur * VSZ;

        // ---- S = Q @ K^T ----
        float s[8][4] = {};
        #pragma unroll
        for (int ks = 0; ks < 8; ks++) {
            const int kk = ks * 8;
            #pragma unroll
            for (int ni = 0; ni < 8; ni++) {
                uint32_t b0 = KPb[(ni * 8 + lr) * KST + kk + lc];
                uint32_t b1 = KPb[(ni * 8 + lr) * KST + kk + lc + 4];
                mma_tf32(s[ni], qf[ks][0], qf[ks][1], qf[ks][2], qf[ks][3], b0, b1);
            }
        }

        if (kt == qt) {
            const int rowA = w * 16 + lr;
            const int rowB = rowA + 8;
            #pragma unroll
            for (int ni = 0; ni < 8; ni++) {
                int c0 = ni * 8 + 2 * lc;
                int c1 = c0 + 1;
                if (c0 > rowA) s[ni][0] = -CUDART_INF_F;
                if (c1 > rowA) s[ni][1] = -CUDART_INF_F;
                if (c0 > rowB) s[ni][2] = -CUDART_INF_F;
                if (c1 > rowB) s[ni][3] = -CUDART_INF_F;
            }
        }

        __syncthreads();                       // all warps done reading K -> reuse as P

        // ---- online softmax (fp32) ----
        float mxA = -CUDART_INF_F, mxB = -CUDART_INF_F;
        #pragma unroll
        for (int ni = 0; ni < 8; ni++) {
            mxA = fmaxf(mxA, fmaxf(s[ni][0], s[ni][1]));
            mxB = fmaxf(mxB, fmaxf(s[ni][2], s[ni][3]));
        }
        #pragma unroll
        for (int off = 1; off <= 2; off <<= 1) {
            mxA = fmaxf(mxA, __shfl_xor_sync(0xffffffffu, mxA, off));
            mxB = fmaxf(mxB, __shfl_xor_sync(0xffffffffu, mxB, off));
        }
        const float mnA = fmaxf(mA, mxA);
        const float mnB = fmaxf(mB, mxB);
        const float cA = __expf(mA - mnA);
        const float cB = __expf(mB - mnB);

        uint32_t* KPw = dynsmem + cur * KPSZ;
        float rsA = 0.f, rsB = 0.f;
        const int rA = (w * 16 + lr) * KST;
        const int rB = rA + 8 * KST;
        #pragma unroll
        for (int ni = 0; ni < 8; ni++) {
            float p0 = __expf(s[ni][0] - mnA);
            float p1 = __expf(s[ni][1] - mnA);
            float p2 = __expf(s[ni][2] - mnB);
            float p3 = __expf(s[ni][3] - mnB);
            rsA += p0 + p1;
            rsB += p2 + p3;
            int col = ni * 8 + 2 * lc;
            *reinterpret_cast<uint2*>(&KPw[rA + col]) = make_uint2(f2tf32(p0), f2tf32(p1));
            *reinterpret_cast<uint2*>(&KPw[rB + col]) = make_uint2(f2tf32(p2), f2tf32(p3));
        }
        #pragma unroll
        for (int off = 1; off <= 2; off <<= 1) {
            rsA += __shfl_xor_sync(0xffffffffu, rsA, off);
            rsB += __shfl_xor_sync(0xffffffffu, rsB, off);
        }
        lA = lA * cA + rsA;  mA = mnA;
        lB = lB * cB + rsB;  mB = mnB;
        #pragma unroll
        for (int ni = 0; ni < 8; ni++) {
            o[ni][0] *= cA;  o[ni][1] *= cA;
            o[ni][2] *= cB;  o[ni][3] *= cB;
        }
        __syncwarp();                          // P rows are per-warp private

        // ---- O += P @ V ----
        #pragma unroll
        for (int ks = 0; ks < 8; ks++) {
            const int kk = ks * 8;
            uint32_t a0 = KPb[rA + kk + lc];
            uint32_t a1 = KPb[rB + kk + lc];
            uint32_t a2 = KPb[rA + kk + lc + 4];
            uint32_t a3 = KPb[rB + kk + lc + 4];
            #pragma unroll
            for (int ni = 0; ni < 8; ni++) {
                uint32_t b0 = Vsb[(kk + lc) * VST + ni * 8 + lr];
                uint32_t b1 = Vsb[(kk + lc + 4) * VST + ni * 8 + lr];
                mma_tf32(o[ni], a0, a1, a2, a3, b0, b1);
            }
        }
    }

    // Epilogue: normalize, tf32-round (feeds outproj A), write
    const float iA = 1.0f / lA;
    const float iB = 1.0f / lB;
    float* obA = g_attn + ((size_t)b * SS + (size_t)qt * 64 + w * 16 + lr) * DD + h * HDIM;
    float* obB = obA + (size_t)8 * DD;
    #pragma unroll
    for (int ni = 0; ni < 8; ni++) {
        int col = ni * 8 + 2 * lc;
        *reinterpret_cast<uint2*>(obA + col) =
            make_uint2(f2tf32(o[ni][0] * iA), f2tf32(o[ni][1] * iA));
        *reinterpret_cast<uint2*>(obB + col) =
            make_uint2(f2tf32(o[ni][2] * iB), f2tf32(o[ni][3] * iB));
    }
}

// ---------------------------------------------------------------------------
extern "C" void kernel_launch(void* const* d_in, const int* in_sizes, int n_in,
                              void* d_out, int out_size)
{
    const float* x    = (const float*)d_in[0];  // (2,2048,1024)
    const float* wqkv = (const float*)d_in[1];  // (1024,3072)
    const float* wout = (const float*)d_in[2];  // (1024,1024)
    float* out = (float*)d_out;                 // (2,2048,1024)

    const int GEMM_SMEM = (2 * ASZ + 2 * BSZ) * 4;       // 71680
    const int ATTN_SMEM = (2 * KPSZ + 2 * VSZ) * 4;      // 71680
    cudaFuncSetAttribute(mma_gemm<0>, cudaFuncAttributeMaxDynamicSharedMemorySize, GEMM_SMEM);
    cudaFuncSetAttribute(mma_gemm<1>, cudaFuncAttributeMaxDynamicSharedMemorySize, GEMM_SMEM);
    cudaFuncSetAttribute(attn_mma,    cudaFuncAttributeMaxDynamicSharedMemorySize, ATTN_SMEM);

    // 0) Round x, w_qkv, w_out to tf32 once
    pre_round<<<2048, 256>>>((const float4*)x, (const float4*)wqkv, (const float4*)wout);

    // 1) QKV projection -> g_qkv (tf32-rounded output)
    mma_gemm<0><<<dim3(NQKV / 128, MROWS / 128), 256, GEMM_SMEM>>>(
        MROWS, NQKV, DD, nullptr);

    // 2) Causal attention -> g_attn (tf32-rounded output)
    attn_mma<<<dim3(SS / 64, HH, BB), 128, ATTN_SMEM>>>();

    // 3) Output projection -> d_out (fp32)
    mma_gemm<1><<<dim3(DD / 128, MROWS / 128), 256, GEMM_SMEM>>>(
        MROWS, DD, DD, out);
}